// round 9
// baseline (speedup 1.0000x reference)
#include <cuda_runtime.h>
#include <math.h>

#define NLOC 1940
#define NPRI 8732
#define BATCH 16
#define TOPK 10
#define NOBJ (BATCH*TOPK)
#define DS 64
#define IMG 300
#define ZWHAT 64
#define CPAD 4
#define TILE 16
#define NTX ((IMG + TILE - 1) / TILE)   // 19

typedef unsigned long long ull;

// ---------------- device scratch (no allocation allowed) -------------------
__device__ __align__(16) float g_decoded[NOBJ * CPAD * DS * DS];   // 10.5 MB
__device__ int   g_order[BATCH * TOPK];
__device__ __align__(16) float g_act3[NOBJ * 32 * 16 * 16];        // 5.2 MB
// duplicated-weight arrays: per (c,o): 8 floats (w0 w0 w1 w1 w2 w2 w3 w3)
__device__ __align__(16) float g_w1d[256 * 128 * 8];
__device__ __align__(16) float g_w2d[128 * 64 * 8];
__device__ __align__(16) float g_w3d[64 * 32 * 8];
__device__ __align__(16) float g_w4d[32 * 16 * 8];

// ---------------- f32x2 helpers --------------------------------------------
__device__ __forceinline__ ull pack2(float lo, float hi) {
    ull r; asm("mov.b64 %0, {%1, %2};" : "=l"(r) : "f"(lo), "f"(hi)); return r;
}
__device__ __forceinline__ void unpack2(ull v, float& a, float& b) {
    asm("mov.b64 {%0, %1}, %2;" : "=f"(a), "=f"(b) : "l"(v));
}
__device__ __forceinline__ ull ffma2(ull a, ull b, ull c) {
    ull d; asm("fma.rn.f32x2 %0, %1, %2, %3;" : "=l"(d) : "l"(a), "l"(b), "l"(c));
    return d;
}
__device__ __forceinline__ ull relu2(ull v) {
    float a, b; unpack2(v, a, b);
    return pack2(fmaxf(a, 0.f), fmaxf(b, 0.f));
}

// ---------------- index maps ------------------------------------------------
__device__ __forceinline__ int prior_to_loc(int i) {
    if (i < 5776) return i >> 2;
    if (i < 7942) return 1444 + (i - 5776) / 6;
    if (i < 8542) return 1805 + (i - 7942) / 6;
    if (i < 8692) return 1905 + (i - 8542) / 6;
    if (i < 8728) return 1930 + ((i - 8692) >> 2);
    return 1939;
}
__device__ __forceinline__ void loc_to_priors(int l, int& start, int& bpl) {
    if (l < 1444)      { start = 4 * l;                 bpl = 4; }
    else if (l < 1805) { start = 5776 + 6 * (l - 1444); bpl = 6; }
    else if (l < 1905) { start = 7942 + 6 * (l - 1805); bpl = 6; }
    else if (l < 1930) { start = 8542 + 6 * (l - 1905); bpl = 6; }
    else               { start = 8692 + 4 * (l - 1930); bpl = 4; }
}
__device__ __forceinline__ bool better(float a, int ia, float b, int ib) {
    return a > b || (a == b && ia < ib);
}
__device__ __forceinline__ void insert3(float v, int i,
                                        float& v0, int& i0, float& v1, int& i1,
                                        float& v2, int& i2) {
    if (better(v, i, v0, i0)) { v2 = v1; i2 = i1; v1 = v0; i1 = i0; v0 = v; i0 = i; }
    else if (better(v, i, v1, i1)) { v2 = v1; i2 = i1; v1 = v; i1 = i; }
    else if (better(v, i, v2, i2)) { v2 = v; i2 = i; }
}

// block-redundant top-3 locations of batch b -> prior index of rank j.
__device__ __forceinline__ int block_topk(const float* __restrict__ z_depth,
                                          int b, int j, float* scratch) {
    const int tid = threadIdx.x;
    float (*sv)[3] = (float(*)[3])scratch;
    int   (*si)[3] = (int(*)[3])(scratch + 256 * 3);

    float v0 = -INFINITY, v1 = -INFINITY, v2 = -INFINITY;
    int   i0 = 0x7fffffff, i1 = 0x7fffffff, i2 = 0x7fffffff;
    const float4* __restrict__ zd4 =
        reinterpret_cast<const float4*>(z_depth + b * NLOC);
    for (int i = tid; i < NLOC / 4; i += 256) {
        const float4 v = __ldg(zd4 + i);
        insert3(v.x, 4 * i + 0, v0, i0, v1, i1, v2, i2);
        insert3(v.y, 4 * i + 1, v0, i0, v1, i1, v2, i2);
        insert3(v.z, 4 * i + 2, v0, i0, v1, i1, v2, i2);
        insert3(v.w, 4 * i + 3, v0, i0, v1, i1, v2, i2);
    }
    sv[tid][0] = v0; sv[tid][1] = v1; sv[tid][2] = v2;
    si[tid][0] = i0; si[tid][1] = i1; si[tid][2] = i2;
    __syncthreads();
    for (int s = 128; s > 0; s >>= 1) {
        if (tid < s) {
            #pragma unroll
            for (int q = 0; q < 3; q++)
                insert3(sv[tid + s][q], si[tid + s][q], v0, i0, v1, i1, v2, i2);
            sv[tid][0] = v0; sv[tid][1] = v1; sv[tid][2] = v2;
            si[tid][0] = i0; si[tid][1] = i1; si[tid][2] = i2;
        }
        __syncthreads();
    }
    __shared__ int s_ord;
    if (tid == 0) {
        int ranks[3] = { i0, i1, i2 };
        int ord = -1, cnt = 0;
        #pragma unroll
        for (int r = 0; r < 3; r++) {
            int start, bpl;
            loc_to_priors(ranks[r], start, bpl);
            if (ord < 0 && j < cnt + bpl) ord = start + (j - cnt);
            cnt += bpl;
        }
        s_ord = ord;
    }
    __syncthreads();
    return s_ord;
}

// ---------------------------------------------------------------------------
// Kernel 0: build duplicated-weight arrays (w -> (w,w)) for W1..W4.
// ---------------------------------------------------------------------------
__global__ void __launch_bounds__(256) prep_kernel(
    const float* __restrict__ W1, const float* __restrict__ W2,
    const float* __restrict__ W3, const float* __restrict__ W4)
{
    const int i = blockIdx.x * 256 + threadIdx.x;  // float4 index over all layers
    const float4* src; ull* dst; int j;
    if (i < 32768)      { src = (const float4*)W1; dst = (ull*)g_w1d; j = i; }
    else if (i < 40960) { src = (const float4*)W2; dst = (ull*)g_w2d; j = i - 32768; }
    else if (i < 43008) { src = (const float4*)W3; dst = (ull*)g_w3d; j = i - 40960; }
    else if (i < 43520) { src = (const float4*)W4; dst = (ull*)g_w4d; j = i - 43008; }
    else return;
    const float4 v = __ldg(src + j);
    dst[j * 4 + 0] = pack2(v.x, v.x);
    dst[j * 4 + 1] = pack2(v.y, v.y);
    dst[j * 4 + 2] = pack2(v.z, v.z);
    dst[j * 4 + 3] = pack2(v.w, v.w);
}

// ---------------------------------------------------------------------------
// dup-weight deconv layer (L1..L3): thread owns (o = t%CO, row y = t/CO).
// Inner loop: 2 x LDG.128 of pre-duplicated weights + NP x LDS.64 + 4*NP FFMA2.
// out[o, 2y+a, 2x+b] = bias[o] + sum_c in[c,y,x] * W[c,o,a,b]
// ---------------------------------------------------------------------------
template<int CI, int CO, int H, int W>
__device__ __forceinline__ void dlayer_dup(const float* __restrict__ in,
                                           float* __restrict__ out,
                                           const float* __restrict__ Wd,
                                           const float* __restrict__ bias)
{
    static_assert(CO * H == 256, "thread mapping");
    constexpr int HW = H * W;
    constexpr int NP = W / 2;
    const int o = threadIdx.x % CO;
    const int y = threadIdx.x / CO;
    const ulonglong2* __restrict__ Wd2 =
        reinterpret_cast<const ulonglong2*>(Wd) + (size_t)o * 2;
    const float bo = __ldg(bias + o);
    const ull bb = pack2(bo, bo);

    ull acc[4][NP];
    #pragma unroll
    for (int q = 0; q < 4; q++)
        #pragma unroll
        for (int pp = 0; pp < NP; pp++) acc[q][pp] = bb;

    const float* iprow = in + y * W;
    #pragma unroll 4
    for (int c = 0; c < CI; c++) {
        const ulonglong2 d0 = __ldg(Wd2 + (size_t)c * CO * 2 + 0);  // (w0w0, w1w1)
        const ulonglong2 d1 = __ldg(Wd2 + (size_t)c * CO * 2 + 1);  // (w2w2, w3w3)
        const ull* __restrict__ ivr =
            reinterpret_cast<const ull*>(iprow + c * HW);
        #pragma unroll
        for (int pp = 0; pp < NP; pp++) {
            const ull iv = ivr[pp];
            acc[0][pp] = ffma2(iv, d0.x, acc[0][pp]);
            acc[1][pp] = ffma2(iv, d0.y, acc[1][pp]);
            acc[2][pp] = ffma2(iv, d1.x, acc[2][pp]);
            acc[3][pp] = ffma2(iv, d1.y, acc[3][pp]);
        }
    }
    float* orow0 = out + (o * 2 * H + 2 * y) * (2 * W);
    float* orow1 = orow0 + 2 * W;
    #pragma unroll
    for (int pp = 0; pp < NP; pp++) {
        float a0l, a0h, a1l, a1h, a2l, a2h, a3l, a3h;
        unpack2(acc[0][pp], a0l, a0h); unpack2(acc[1][pp], a1l, a1h);
        unpack2(acc[2][pp], a2l, a2h); unpack2(acc[3][pp], a3l, a3h);
        const float4 r0 = make_float4(fmaxf(a0l, 0.f), fmaxf(a1l, 0.f),
                                      fmaxf(a0h, 0.f), fmaxf(a1h, 0.f));
        const float4 r1 = make_float4(fmaxf(a2l, 0.f), fmaxf(a3l, 0.f),
                                      fmaxf(a2h, 0.f), fmaxf(a3h, 0.f));
        *reinterpret_cast<float4*>(orow0 + 4 * pp) = r0;
        *reinterpret_cast<float4*>(orow1 + 4 * pp) = r1;
    }
}

// ---------------------------------------------------------------------------
// Kernel A: topk + z_what gather + L0..L3; writes g_act3[m] = [32][16][16].
// L0 uses the quadrant-pair trick: W0's float4 = (w0,w1 | w2,w3) as two
// 64-bit halves; accumulate (out00,out01) and (out10,out11) pairs directly.
// ---------------------------------------------------------------------------
__global__ void __launch_bounds__(256) decodeA_kernel(
    const float* __restrict__ z_depth,
    const float* __restrict__ z_what,
    const float* __restrict__ W0, const float* __restrict__ b0,
    const float* __restrict__ b1, const float* __restrict__ b2,
    const float* __restrict__ b3)
{
    __shared__ __align__(16) float bufA[2048];
    __shared__ __align__(16) float bufB[4096];

    const int m = blockIdx.x;
    const int b = m / TOPK;
    const int j = m % TOPK;

    const int ord = block_topk(z_depth, b, j, bufB);
    if (threadIdx.x == 0) g_order[m] = ord;

    const int loc = prior_to_loc(ord);
    const float* src = z_what + (size_t)(b * NLOC + loc) * ZWHAT;
    if (threadIdx.x < ZWHAT) bufA[threadIdx.x] = src[threadIdx.x];
    __syncthreads();

    // ---- L0: 64 -> 256 ch, 1x1 -> 2x2 (quadrant pairs) ----
    {
        const int o = threadIdx.x;    // 256 channels
        const ulonglong2* __restrict__ W02 =
            reinterpret_cast<const ulonglong2*>(W0);
        const float bo = __ldg(b0 + o);
        ull acc01 = pack2(bo, bo), acc23 = acc01;
        #pragma unroll 8
        for (int c = 0; c < 64; c++) {
            const ulonglong2 wq = __ldg(W02 + c * 256 + o);
            const ull ivd = pack2(bufA[c], bufA[c]);
            acc01 = ffma2(ivd, wq.x, acc01);
            acc23 = ffma2(ivd, wq.y, acc23);
        }
        __syncthreads();
        ull* ob = reinterpret_cast<ull*>(bufB) + o * 2;
        ob[0] = relu2(acc01);   // out[o][0][0..1]
        ob[1] = relu2(acc23);   // out[o][1][0..1]
    }
    __syncthreads();

    dlayer_dup<256, 128, 2, 2>(bufB, bufA, g_w1d, b1); __syncthreads(); // 128x4x4
    dlayer_dup<128,  64, 4, 4>(bufA, bufB, g_w2d, b2); __syncthreads(); // 64x8x8
    dlayer_dup< 64,  32, 8, 8>(bufB, g_act3 + (size_t)m * 8192, g_w3d, b3); // 32x16x16
}

// ---------------------------------------------------------------------------
// Kernel B: L4 + L5 for one (object, row-slice) pair. 4 blocks per object.
// Block (m, k): L4 src rows [4k,4k+4) -> L4 out rows [8k,8k+8)
//            -> L5 out (final) rows [16k,16k+16). Stride-2 deconv => no overlap.
// ---------------------------------------------------------------------------
__global__ void __launch_bounds__(256) decodeB_kernel(
    const float* __restrict__ b4,
    const float* __restrict__ W5, const float* __restrict__ b5)
{
    __shared__ __align__(16) float s_in[32 * 4 * 16];    // L4 src slice, 8 KB
    __shared__ __align__(16) float s_mid[16 * 8 * 32];   // L4 out slice, 16 KB
    __shared__ __align__(16) float s_w5[16 * 3 * 4];     // W5 float4 per (c,o)
    __shared__ __align__(16) float s_b5[4];

    const int m = blockIdx.x >> 2;
    const int k = blockIdx.x & 3;
    const int tid = threadIdx.x;

    // load L4 src slice (rows 4k..4k+4 of each of 32 channels)
    {
        const float4* __restrict__ a4 =
            reinterpret_cast<const float4*>(g_act3) + (size_t)m * 2048;
        float4* s4 = reinterpret_cast<float4*>(s_in);
        #pragma unroll
        for (int f = tid; f < 512; f += 256) {
            const int c = f >> 4, rr = (f >> 2) & 3, xq = f & 3;
            s4[f] = __ldg(a4 + c * 64 + (4 * k + rr) * 4 + xq);
        }
    }
    if (tid < 192) s_w5[tid] = __ldg(W5 + tid);
    if (tid < 3)   s_b5[tid] = __ldg(b5 + tid);
    __syncthreads();

    // ---- L4: 32 -> 16 ch, slice rows: thread = (o, y_local, x-quarter) ----
    {
        const int o  = tid & 15;
        const int y  = (tid >> 4) & 3;
        const int xq = tid >> 6;          // 0..3, pixels x0 = 4*xq .. +3
        const int x0 = xq * 4;
        const ulonglong2* __restrict__ Wd2 =
            reinterpret_cast<const ulonglong2*>(g_w4d) + o * 2;
        const float bo = __ldg(b4 + o);
        const ull bb = pack2(bo, bo);
        ull acc[4][2];
        #pragma unroll
        for (int q = 0; q < 4; q++) { acc[q][0] = bb; acc[q][1] = bb; }

        #pragma unroll 4
        for (int c = 0; c < 32; c++) {
            const ulonglong2 d0 = __ldg(Wd2 + c * 32 + 0);
            const ulonglong2 d1 = __ldg(Wd2 + c * 32 + 1);
            const ull* ivr = reinterpret_cast<const ull*>(s_in + c * 64 + y * 16 + x0);
            #pragma unroll
            for (int pp = 0; pp < 2; pp++) {
                const ull iv = ivr[pp];
                acc[0][pp] = ffma2(iv, d0.x, acc[0][pp]);
                acc[1][pp] = ffma2(iv, d0.y, acc[1][pp]);
                acc[2][pp] = ffma2(iv, d1.x, acc[2][pp]);
                acc[3][pp] = ffma2(iv, d1.y, acc[3][pp]);
            }
        }
        float* orow0 = s_mid + o * 256 + (2 * y) * 32 + 2 * x0;
        float* orow1 = orow0 + 32;
        #pragma unroll
        for (int pp = 0; pp < 2; pp++) {
            float a0l, a0h, a1l, a1h, a2l, a2h, a3l, a3h;
            unpack2(acc[0][pp], a0l, a0h); unpack2(acc[1][pp], a1l, a1h);
            unpack2(acc[2][pp], a2l, a2h); unpack2(acc[3][pp], a3l, a3h);
            *reinterpret_cast<float4*>(orow0 + 4 * pp) =
                make_float4(fmaxf(a0l, 0.f), fmaxf(a1l, 0.f), fmaxf(a0h, 0.f), fmaxf(a1h, 0.f));
            *reinterpret_cast<float4*>(orow1 + 4 * pp) =
                make_float4(fmaxf(a2l, 0.f), fmaxf(a3l, 0.f), fmaxf(a2h, 0.f), fmaxf(a3h, 0.f));
        }
    }
    __syncthreads();

    // ---- L5: 16 -> 3 ch, sigmoid, CPAD-interleaved texels (quadrant pairs) ----
    {
        const int sy = tid >> 5;          // 0..7  (local src row)
        const int sx = tid & 31;          // 0..31 (src col)
        const ulonglong2* __restrict__ w5u =
            reinterpret_cast<const ulonglong2*>(s_w5);
        ull acc01[3], acc23[3];
        #pragma unroll
        for (int o = 0; o < 3; o++) {
            acc01[o] = pack2(s_b5[o], s_b5[o]);
            acc23[o] = acc01[o];
        }
        #pragma unroll 4
        for (int c = 0; c < 16; c++) {
            const float iv = s_mid[c * 256 + sy * 32 + sx];
            const ull ivd = pack2(iv, iv);
            #pragma unroll
            for (int o = 0; o < 3; o++) {
                const ulonglong2 wq = w5u[c * 3 + o];
                acc01[o] = ffma2(ivd, wq.x, acc01[o]);
                acc23[o] = ffma2(ivd, wq.y, acc23[o]);
            }
        }
        float r00[3], r01[3], r10[3], r11[3];
        #pragma unroll
        for (int o = 0; o < 3; o++) {
            float v00, v01, v10, v11;
            unpack2(acc01[o], v00, v01);
            unpack2(acc23[o], v10, v11);
            r00[o] = 1.0f / (1.0f + __expf(-v00));
            r01[o] = 1.0f / (1.0f + __expf(-v01));
            r10[o] = 1.0f / (1.0f + __expf(-v10));
            r11[o] = 1.0f / (1.0f + __expf(-v11));
        }
        float4* g4 = reinterpret_cast<float4*>(g_decoded) + (size_t)m * DS * DS;
        const int row0 = 16 * k + 2 * sy;
        const int col0 = 2 * sx;
        g4[row0 * DS + col0]       = make_float4(r00[0], r00[1], r00[2], 0.f);
        g4[row0 * DS + col0 + 1]   = make_float4(r01[0], r01[1], r01[2], 0.f);
        g4[(row0 + 1) * DS + col0]     = make_float4(r10[0], r10[1], r10[2], 0.f);
        g4[(row0 + 1) * DS + col0 + 1] = make_float4(r11[0], r11[1], r11[2], 0.f);
    }
}

// ---------------------------------------------------------------------------
// Kernel C: fused STN + depth-ordered first-nonzero compositing (unchanged).
// ---------------------------------------------------------------------------
__global__ void __launch_bounds__(256) composite_kernel(
    const float* __restrict__ z_where,
    const int*   __restrict__ z_present,
    float* __restrict__ out)
{
    const int b = blockIdx.y;
    const int tx0 = (blockIdx.x % NTX) * TILE;
    const int ty0 = (blockIdx.x / NTX) * TILE;

    __shared__ float s_sx[TOPK], s_ox[TOPK], s_sy[TOPK], s_oy[TOPK];
    __shared__ int   s_flag[TOPK];
    __shared__ int   s_list[TOPK];
    __shared__ int   s_nc;

    const int tid = threadIdx.x;
    if (tid < TOPK) {
        const int ord = g_order[b * TOPK + tid];
        const float* zw = z_where + (size_t)(b * NPRI + ord) * 4;
        const float cx = zw[0], cy = zw[1];
        const float w = zw[2] + 1e-6f, h = zw[3] + 1e-6f;
        const float half = (float)DS * 0.5f;
        const float xsn = half / w;
        const float ysn = half / h;
        const float sx = xsn * (2.0f / (float)IMG);
        const float ox = half - 0.5f
                         + xsn * ((1.0f / (float)IMG - 1.0f) - (2.0f * cx - 1.0f));
        const float sy = ysn * (2.0f / (float)IMG);
        const float oy = half - 0.5f
                         + ysn * ((1.0f / (float)IMG - 1.0f) - (2.0f * cy - 1.0f));
        s_sx[tid] = sx; s_ox[tid] = ox; s_sy[tid] = sy; s_oy[tid] = oy;
        const float ix_lo = fmaf((float)tx0, sx, ox);
        const float ix_hi = fmaf((float)(tx0 + TILE - 1), sx, ox);
        const float iy_lo = fmaf((float)ty0, sy, oy);
        const float iy_hi = fmaf((float)(ty0 + TILE - 1), sy, oy);
        const bool pres = (z_present[b * NPRI + ord] == 1);
        s_flag[tid] = (pres &&
                       ix_hi >= -1.01f && ix_lo < 64.01f &&
                       iy_hi >= -1.01f && iy_lo < 64.01f) ? 1 : 0;
    }
    __syncthreads();
    if (tid == 0) {
        int nc = 0;
        #pragma unroll
        for (int k = 0; k < TOPK; k++)
            if (s_flag[k]) s_list[nc++] = k;
        s_nc = nc;
    }
    __syncthreads();

    const int x = tx0 + (tid % TILE);
    const int y = ty0 + (tid / TILE);
    if (x >= IMG || y >= IMG) return;
    const float fx = (float)x, fy = (float)y;

    float r0 = 0.0f, r1 = 0.0f, r2 = 0.0f;
    int done = 0;
    const int nc = s_nc;

    for (int kk = 0; kk < nc; kk++) {
        const int k = s_list[kk];
        const float ix = fmaf(fx, s_sx[k], s_ox[k]);
        const float iy = fmaf(fy, s_sy[k], s_oy[k]);
        const float ix0f = floorf(ix), iy0f = floorf(iy);
        if (!(ix0f >= -1.0f && ix0f <= 63.0f && iy0f >= -1.0f && iy0f <= 63.0f))
            continue;
        const float wx1 = ix - ix0f, wy1 = iy - iy0f;
        const float wx0 = 1.0f - wx1, wy0 = 1.0f - wy1;
        const int ix0 = (int)ix0f, iy0 = (int)iy0f;
        const bool vx0 = (ix0 >= 0), vx1 = (ix0 <= 62);
        const bool vy0 = (iy0 >= 0), vy1 = (iy0 <= 62);
        const float w00 = (vy0 && vx0) ? wy0 * wx0 : 0.0f;
        const float w01 = (vy0 && vx1) ? wy0 * wx1 : 0.0f;
        const float w10 = (vy1 && vx0) ? wy1 * wx0 : 0.0f;
        const float w11 = (vy1 && vx1) ? wy1 * wx1 : 0.0f;
        const int x0c = max(ix0, 0),     x1c = min(ix0 + 1, DS - 1);
        const int y0c = max(iy0, 0),     y1c = min(iy0 + 1, DS - 1);
        const int i00 = y0c * DS + x0c, i01 = y0c * DS + x1c;
        const int i10 = y1c * DS + x0c, i11 = y1c * DS + x1c;
        const float4* __restrict__ base = reinterpret_cast<const float4*>(g_decoded)
                                          + (size_t)(b * TOPK + k) * DS * DS;
        const float4 t00 = __ldg(base + i00);
        const float4 t01 = __ldg(base + i01);
        const float4 t10 = __ldg(base + i10);
        const float4 t11 = __ldg(base + i11);

        const float s0 = t00.x * w00 + t01.x * w01 + t10.x * w10 + t11.x * w11;
        const float s1 = t00.y * w00 + t01.y * w01 + t10.y * w10 + t11.y * w11;
        const float s2 = t00.z * w00 + t01.z * w01 + t10.z * w10 + t11.z * w11;

        if (!(done & 1) && s0 != 0.0f) { r0 = s0; done |= 1; }
        if (!(done & 2) && s1 != 0.0f) { r1 = s1; done |= 2; }
        if (!(done & 4) && s2 != 0.0f) { r2 = s2; done |= 4; }
        if (done == 7) break;
    }

    const size_t pix = (size_t)y * IMG + x;
    out[((size_t)(b * 3 + 0) * IMG * IMG) + pix] = r0;
    out[((size_t)(b * 3 + 1) * IMG * IMG) + pix] = r1;
    out[((size_t)(b * 3 + 2) * IMG * IMG) + pix] = r2;
}

// ---------------------------------------------------------------------------
extern "C" void kernel_launch(void* const* d_in, const int* in_sizes, int n_in,
                              void* d_out, int out_size)
{
    const float* z_what    = (const float*)d_in[0];
    const float* z_where   = (const float*)d_in[1];
    const int*   z_present = (const int*)  d_in[2];
    const float* z_depth   = (const float*)d_in[3];
    const float* W0 = (const float*)d_in[4];  const float* b0 = (const float*)d_in[5];
    const float* W1 = (const float*)d_in[6];  const float* b1 = (const float*)d_in[7];
    const float* W2 = (const float*)d_in[8];  const float* b2 = (const float*)d_in[9];
    const float* W3 = (const float*)d_in[10]; const float* b3 = (const float*)d_in[11];
    const float* W4 = (const float*)d_in[12]; const float* b4 = (const float*)d_in[13];
    const float* W5 = (const float*)d_in[14]; const float* b5 = (const float*)d_in[15];
    float* out = (float*)d_out;

    prep_kernel<<<(43520 + 255) / 256, 256>>>(W1, W2, W3, W4);

    decodeA_kernel<<<NOBJ, 256>>>(z_depth, z_what, W0, b0, b1, b2, b3);

    decodeB_kernel<<<NOBJ * 4, 256>>>(b4, W5, b5);

    dim3 cgrid(NTX * NTX, BATCH);
    composite_kernel<<<cgrid, 256>>>(z_where, z_present, out);
}

// round 10
// speedup vs baseline: 1.6844x; 1.6844x over previous
#include <cuda_runtime.h>
#include <math.h>

#define NLOC 1940
#define NPRI 8732
#define BATCH 16
#define TOPK 10
#define NOBJ (BATCH*TOPK)
#define DS 64
#define IMG 300
#define ZWHAT 64
#define CPAD 4
#define TILE 16
#define NTX ((IMG + TILE - 1) / TILE)   // 19

typedef unsigned long long ull;

// ---------------- device scratch (no allocation allowed) -------------------
__device__ __align__(16) float g_decoded[NOBJ * CPAD * DS * DS];   // 10.5 MB
__device__ int   g_order[BATCH * TOPK];
__device__ __align__(16) float g_act3[NOBJ * 32 * 16 * 16];        // 5.2 MB

// ---------------- f32x2 helpers --------------------------------------------
__device__ __forceinline__ ull pack2(float lo, float hi) {
    ull r; asm("mov.b64 %0, {%1, %2};" : "=l"(r) : "f"(lo), "f"(hi)); return r;
}
__device__ __forceinline__ void unpack2(ull v, float& a, float& b) {
    asm("mov.b64 {%0, %1}, %2;" : "=f"(a), "=f"(b) : "l"(v));
}
__device__ __forceinline__ ull ffma2(ull a, ull b, ull c) {
    ull d; asm("fma.rn.f32x2 %0, %1, %2, %3;" : "=l"(d) : "l"(a), "l"(b), "l"(c));
    return d;
}
__device__ __forceinline__ ull relu2(ull v) {
    float a, b; unpack2(v, a, b);
    return pack2(fmaxf(a, 0.f), fmaxf(b, 0.f));
}

// ---------------- index maps ------------------------------------------------
__device__ __forceinline__ int prior_to_loc(int i) {
    if (i < 5776) return i >> 2;
    if (i < 7942) return 1444 + (i - 5776) / 6;
    if (i < 8542) return 1805 + (i - 7942) / 6;
    if (i < 8692) return 1905 + (i - 8542) / 6;
    if (i < 8728) return 1930 + ((i - 8692) >> 2);
    return 1939;
}
__device__ __forceinline__ void loc_to_priors(int l, int& start, int& bpl) {
    if (l < 1444)      { start = 4 * l;                 bpl = 4; }
    else if (l < 1805) { start = 5776 + 6 * (l - 1444); bpl = 6; }
    else if (l < 1905) { start = 7942 + 6 * (l - 1805); bpl = 6; }
    else if (l < 1930) { start = 8542 + 6 * (l - 1905); bpl = 6; }
    else               { start = 8692 + 4 * (l - 1930); bpl = 4; }
}
__device__ __forceinline__ bool better(float a, int ia, float b, int ib) {
    return a > b || (a == b && ia < ib);
}
__device__ __forceinline__ void insert3(float v, int i,
                                        float& v0, int& i0, float& v1, int& i1,
                                        float& v2, int& i2) {
    if (better(v, i, v0, i0)) { v2 = v1; i2 = i1; v1 = v0; i1 = i0; v0 = v; i0 = i; }
    else if (better(v, i, v1, i1)) { v2 = v1; i2 = i1; v1 = v; i1 = i; }
    else if (better(v, i, v2, i2)) { v2 = v; i2 = i; }
}

// block-redundant top-3 locations of batch b -> prior index of rank j.
__device__ __forceinline__ int block_topk(const float* __restrict__ z_depth,
                                          int b, int j, float* scratch) {
    const int tid = threadIdx.x;
    float (*sv)[3] = (float(*)[3])scratch;
    int   (*si)[3] = (int(*)[3])(scratch + 256 * 3);

    float v0 = -INFINITY, v1 = -INFINITY, v2 = -INFINITY;
    int   i0 = 0x7fffffff, i1 = 0x7fffffff, i2 = 0x7fffffff;
    const float4* __restrict__ zd4 =
        reinterpret_cast<const float4*>(z_depth + b * NLOC);
    for (int i = tid; i < NLOC / 4; i += 256) {
        const float4 v = __ldg(zd4 + i);
        insert3(v.x, 4 * i + 0, v0, i0, v1, i1, v2, i2);
        insert3(v.y, 4 * i + 1, v0, i0, v1, i1, v2, i2);
        insert3(v.z, 4 * i + 2, v0, i0, v1, i1, v2, i2);
        insert3(v.w, 4 * i + 3, v0, i0, v1, i1, v2, i2);
    }
    sv[tid][0] = v0; sv[tid][1] = v1; sv[tid][2] = v2;
    si[tid][0] = i0; si[tid][1] = i1; si[tid][2] = i2;
    __syncthreads();
    for (int s = 128; s > 0; s >>= 1) {
        if (tid < s) {
            #pragma unroll
            for (int q = 0; q < 3; q++)
                insert3(sv[tid + s][q], si[tid + s][q], v0, i0, v1, i1, v2, i2);
            sv[tid][0] = v0; sv[tid][1] = v1; sv[tid][2] = v2;
            si[tid][0] = i0; si[tid][1] = i1; si[tid][2] = i2;
        }
        __syncthreads();
    }
    __shared__ int s_ord;
    if (tid == 0) {
        int ranks[3] = { i0, i1, i2 };
        int ord = -1, cnt = 0;
        #pragma unroll
        for (int r = 0; r < 3; r++) {
            int start, bpl;
            loc_to_priors(ranks[r], start, bpl);
            if (ord < 0 && j < cnt + bpl) ord = start + (j - cnt);
            cnt += bpl;
        }
        s_ord = ord;
    }
    __syncthreads();
    return s_ord;
}

// ---------------------------------------------------------------------------
// Quadrant-pair deconv layer: thread owns (o = t%CO, row y = t/CO).
// Native weight float4 per (c,o) = (w0,w1 | w2,w3) as two 64-bit halves.
// acc01[x] = (out[o][2y][2x], out[o][2y][2x+1]); acc23[x] = row 2y+1.
// Per c: 1 LDG.128 + W/2 LDS.64 + W pack-MOV + 2W FFMA2.
// ---------------------------------------------------------------------------
template<int CI, int CO, int H, int W>
__device__ __forceinline__ void dlayer_q(const float* __restrict__ in,
                                         float* __restrict__ out,
                                         const float* __restrict__ Wt,
                                         const float* __restrict__ bias)
{
    static_assert(CO * H == 256, "thread mapping");
    constexpr int HW = H * W;
    const int o = threadIdx.x % CO;
    const int y = threadIdx.x / CO;
    const ulonglong2* __restrict__ Wq =
        reinterpret_cast<const ulonglong2*>(Wt);
    const float bo = __ldg(bias + o);
    const ull bb = pack2(bo, bo);

    ull acc01[W], acc23[W];
    #pragma unroll
    for (int x = 0; x < W; x++) { acc01[x] = bb; acc23[x] = bb; }

    const float* iprow = in + y * W;
    #pragma unroll 4
    for (int c = 0; c < CI; c++) {
        const ulonglong2 wq = __ldg(Wq + c * CO + o);
        const ull* __restrict__ ivp =
            reinterpret_cast<const ull*>(iprow + c * HW);
        #pragma unroll
        for (int pp = 0; pp < W / 2; pp++) {
            float i0, i1; unpack2(ivp[pp], i0, i1);
            const ull d0 = pack2(i0, i0);
            const ull d1 = pack2(i1, i1);
            acc01[2 * pp]     = ffma2(d0, wq.x, acc01[2 * pp]);
            acc23[2 * pp]     = ffma2(d0, wq.y, acc23[2 * pp]);
            acc01[2 * pp + 1] = ffma2(d1, wq.x, acc01[2 * pp + 1]);
            acc23[2 * pp + 1] = ffma2(d1, wq.y, acc23[2 * pp + 1]);
        }
    }
    ull* orow0 = reinterpret_cast<ull*>(out + (o * 2 * H + 2 * y) * (2 * W));
    ull* orow1 = reinterpret_cast<ull*>(out + (o * 2 * H + 2 * y + 1) * (2 * W));
    #pragma unroll
    for (int x = 0; x < W; x++) {
        orow0[x] = relu2(acc01[x]);
        orow1[x] = relu2(acc23[x]);
    }
}

// ---------------------------------------------------------------------------
// Kernel A: topk + z_what gather + L0..L3; writes g_act3[m] = [32][16][16].
// ---------------------------------------------------------------------------
__global__ void __launch_bounds__(256) decodeA_kernel(
    const float* __restrict__ z_depth,
    const float* __restrict__ z_what,
    const float* __restrict__ W0, const float* __restrict__ b0,
    const float* __restrict__ W1, const float* __restrict__ b1,
    const float* __restrict__ W2, const float* __restrict__ b2,
    const float* __restrict__ W3, const float* __restrict__ b3)
{
    __shared__ __align__(16) float bufA[2048];
    __shared__ __align__(16) float bufB[4096];

    const int m = blockIdx.x;
    const int b = m / TOPK;
    const int j = m % TOPK;

    const int ord = block_topk(z_depth, b, j, bufB);
    if (threadIdx.x == 0) g_order[m] = ord;

    const int loc = prior_to_loc(ord);
    const float* src = z_what + (size_t)(b * NLOC + loc) * ZWHAT;
    if (threadIdx.x < ZWHAT) bufA[threadIdx.x] = src[threadIdx.x];
    __syncthreads();

    // ---- L0: 64 -> 256 ch, 1x1 -> 2x2 (quadrant pairs, native W0) ----
    {
        const int o = threadIdx.x;    // 256 channels
        const ulonglong2* __restrict__ W0q =
            reinterpret_cast<const ulonglong2*>(W0);
        const float bo = __ldg(b0 + o);
        ull acc01 = pack2(bo, bo), acc23 = acc01;
        #pragma unroll 8
        for (int c = 0; c < 64; c++) {
            const ulonglong2 wq = __ldg(W0q + c * 256 + o);
            const ull ivd = pack2(bufA[c], bufA[c]);
            acc01 = ffma2(ivd, wq.x, acc01);
            acc23 = ffma2(ivd, wq.y, acc23);
        }
        __syncthreads();
        ull* ob = reinterpret_cast<ull*>(bufB) + o * 2;
        ob[0] = relu2(acc01);   // out[o][0][0..1]
        ob[1] = relu2(acc23);   // out[o][1][0..1]
    }
    __syncthreads();

    dlayer_q<256, 128, 2, 2>(bufB, bufA, W1, b1); __syncthreads(); // 128x4x4
    dlayer_q<128,  64, 4, 4>(bufA, bufB, W2, b2); __syncthreads(); // 64x8x8
    dlayer_q< 64,  32, 8, 8>(bufB, g_act3 + (size_t)m * 8192, W3, b3); // 32x16x16
}

// ---------------------------------------------------------------------------
// Kernel B: L4 + L5 for one (object, row-slice). 4 blocks per object.
// Block (m, k): L4 src rows [4k,4k+4) -> final rows [16k,16k+16).
// ---------------------------------------------------------------------------
__global__ void __launch_bounds__(256) decodeB_kernel(
    const float* __restrict__ W4, const float* __restrict__ b4,
    const float* __restrict__ W5, const float* __restrict__ b5)
{
    __shared__ __align__(16) float s_in[32 * 4 * 16];    // L4 src slice, 8 KB
    __shared__ __align__(16) float s_mid[16 * 8 * 32];   // L4 out slice, 16 KB
    __shared__ __align__(16) float s_w5[16 * 3 * 4];     // W5 float4 per (c,o)
    __shared__ __align__(16) float s_b5[4];

    const int m = blockIdx.x >> 2;
    const int k = blockIdx.x & 3;
    const int tid = threadIdx.x;

    // load L4 src slice (rows 4k..4k+4 of each of 32 channels)
    {
        const float4* __restrict__ a4 =
            reinterpret_cast<const float4*>(g_act3) + (size_t)m * 2048;
        float4* s4 = reinterpret_cast<float4*>(s_in);
        #pragma unroll
        for (int f = tid; f < 512; f += 256) {
            const int c = f >> 4, rr = (f >> 2) & 3, xq = f & 3;
            s4[f] = __ldg(a4 + c * 64 + (4 * k + rr) * 4 + xq);
        }
    }
    if (tid < 192) s_w5[tid] = __ldg(W5 + tid);
    if (tid < 3)   s_b5[tid] = __ldg(b5 + tid);
    __syncthreads();

    // ---- L4: 32 -> 16 ch (quadrant pairs, native W4) ----
    // thread = (o = tid&15, y = (tid>>4)&3, xq = tid>>6); owns pixels x0..x0+3
    {
        const int o  = tid & 15;
        const int y  = (tid >> 4) & 3;
        const int x0 = (tid >> 6) * 4;
        const ulonglong2* __restrict__ W4q =
            reinterpret_cast<const ulonglong2*>(W4);
        const float bo = __ldg(b4 + o);
        const ull bb = pack2(bo, bo);
        ull acc01[4], acc23[4];
        #pragma unroll
        for (int p = 0; p < 4; p++) { acc01[p] = bb; acc23[p] = bb; }

        #pragma unroll 4
        for (int c = 0; c < 32; c++) {
            const ulonglong2 wq = __ldg(W4q + c * 16 + o);
            const ull* __restrict__ ivp =
                reinterpret_cast<const ull*>(s_in + c * 64 + y * 16 + x0);
            #pragma unroll
            for (int pp = 0; pp < 2; pp++) {
                float i0, i1; unpack2(ivp[pp], i0, i1);
                const ull d0 = pack2(i0, i0);
                const ull d1 = pack2(i1, i1);
                acc01[2 * pp]     = ffma2(d0, wq.x, acc01[2 * pp]);
                acc23[2 * pp]     = ffma2(d0, wq.y, acc23[2 * pp]);
                acc01[2 * pp + 1] = ffma2(d1, wq.x, acc01[2 * pp + 1]);
                acc23[2 * pp + 1] = ffma2(d1, wq.y, acc23[2 * pp + 1]);
            }
        }
        // s_mid layout [o][row(8)][col(32)]
        #pragma unroll
        for (int p = 0; p < 4; p++) {
            const int col = 2 * (x0 + p);
            *reinterpret_cast<ull*>(s_mid + o * 256 + (2 * y) * 32 + col)     = relu2(acc01[p]);
            *reinterpret_cast<ull*>(s_mid + o * 256 + (2 * y + 1) * 32 + col) = relu2(acc23[p]);
        }
    }
    __syncthreads();

    // ---- L5: 16 -> 3 ch, sigmoid, CPAD-interleaved texels (quadrant pairs) ----
    {
        const int sy = tid >> 5;          // 0..7  (local src row)
        const int sx = tid & 31;          // 0..31 (src col)
        const ulonglong2* __restrict__ w5u =
            reinterpret_cast<const ulonglong2*>(s_w5);
        ull acc01[3], acc23[3];
        #pragma unroll
        for (int o = 0; o < 3; o++) {
            acc01[o] = pack2(s_b5[o], s_b5[o]);
            acc23[o] = acc01[o];
        }
        #pragma unroll 4
        for (int c = 0; c < 16; c++) {
            const float iv = s_mid[c * 256 + sy * 32 + sx];
            const ull ivd = pack2(iv, iv);
            #pragma unroll
            for (int o = 0; o < 3; o++) {
                const ulonglong2 wq = w5u[c * 3 + o];
                acc01[o] = ffma2(ivd, wq.x, acc01[o]);
                acc23[o] = ffma2(ivd, wq.y, acc23[o]);
            }
        }
        float r00[3], r01[3], r10[3], r11[3];
        #pragma unroll
        for (int o = 0; o < 3; o++) {
            float v00, v01, v10, v11;
            unpack2(acc01[o], v00, v01);
            unpack2(acc23[o], v10, v11);
            r00[o] = 1.0f / (1.0f + __expf(-v00));
            r01[o] = 1.0f / (1.0f + __expf(-v01));
            r10[o] = 1.0f / (1.0f + __expf(-v10));
            r11[o] = 1.0f / (1.0f + __expf(-v11));
        }
        float4* g4 = reinterpret_cast<float4*>(g_decoded) + (size_t)m * DS * DS;
        const int row0 = 16 * k + 2 * sy;
        const int col0 = 2 * sx;
        g4[row0 * DS + col0]           = make_float4(r00[0], r00[1], r00[2], 0.f);
        g4[row0 * DS + col0 + 1]       = make_float4(r01[0], r01[1], r01[2], 0.f);
        g4[(row0 + 1) * DS + col0]     = make_float4(r10[0], r10[1], r10[2], 0.f);
        g4[(row0 + 1) * DS + col0 + 1] = make_float4(r11[0], r11[1], r11[2], 0.f);
    }
}

// ---------------------------------------------------------------------------
// Kernel C: fused STN + depth-ordered first-nonzero compositing (unchanged).
// ---------------------------------------------------------------------------
__global__ void __launch_bounds__(256) composite_kernel(
    const float* __restrict__ z_where,
    const int*   __restrict__ z_present,
    float* __restrict__ out)
{
    const int b = blockIdx.y;
    const int tx0 = (blockIdx.x % NTX) * TILE;
    const int ty0 = (blockIdx.x / NTX) * TILE;

    __shared__ float s_sx[TOPK], s_ox[TOPK], s_sy[TOPK], s_oy[TOPK];
    __shared__ int   s_flag[TOPK];
    __shared__ int   s_list[TOPK];
    __shared__ int   s_nc;

    const int tid = threadIdx.x;
    if (tid < TOPK) {
        const int ord = g_order[b * TOPK + tid];
        const float* zw = z_where + (size_t)(b * NPRI + ord) * 4;
        const float cx = zw[0], cy = zw[1];
        const float w = zw[2] + 1e-6f, h = zw[3] + 1e-6f;
        const float half = (float)DS * 0.5f;
        const float xsn = half / w;
        const float ysn = half / h;
        const float sx = xsn * (2.0f / (float)IMG);
        const float ox = half - 0.5f
                         + xsn * ((1.0f / (float)IMG - 1.0f) - (2.0f * cx - 1.0f));
        const float sy = ysn * (2.0f / (float)IMG);
        const float oy = half - 0.5f
                         + ysn * ((1.0f / (float)IMG - 1.0f) - (2.0f * cy - 1.0f));
        s_sx[tid] = sx; s_ox[tid] = ox; s_sy[tid] = sy; s_oy[tid] = oy;
        const float ix_lo = fmaf((float)tx0, sx, ox);
        const float ix_hi = fmaf((float)(tx0 + TILE - 1), sx, ox);
        const float iy_lo = fmaf((float)ty0, sy, oy);
        const float iy_hi = fmaf((float)(ty0 + TILE - 1), sy, oy);
        const bool pres = (z_present[b * NPRI + ord] == 1);
        s_flag[tid] = (pres &&
                       ix_hi >= -1.01f && ix_lo < 64.01f &&
                       iy_hi >= -1.01f && iy_lo < 64.01f) ? 1 : 0;
    }
    __syncthreads();
    if (tid == 0) {
        int nc = 0;
        #pragma unroll
        for (int k = 0; k < TOPK; k++)
            if (s_flag[k]) s_list[nc++] = k;
        s_nc = nc;
    }
    __syncthreads();

    const int x = tx0 + (tid % TILE);
    const int y = ty0 + (tid / TILE);
    if (x >= IMG || y >= IMG) return;
    const float fx = (float)x, fy = (float)y;

    float r0 = 0.0f, r1 = 0.0f, r2 = 0.0f;
    int done = 0;
    const int nc = s_nc;

    for (int kk = 0; kk < nc; kk++) {
        const int k = s_list[kk];
        const float ix = fmaf(fx, s_sx[k], s_ox[k]);
        const float iy = fmaf(fy, s_sy[k], s_oy[k]);
        const float ix0f = floorf(ix), iy0f = floorf(iy);
        if (!(ix0f >= -1.0f && ix0f <= 63.0f && iy0f >= -1.0f && iy0f <= 63.0f))
            continue;
        const float wx1 = ix - ix0f, wy1 = iy - iy0f;
        const float wx0 = 1.0f - wx1, wy0 = 1.0f - wy1;
        const int ix0 = (int)ix0f, iy0 = (int)iy0f;
        const bool vx0 = (ix0 >= 0), vx1 = (ix0 <= 62);
        const bool vy0 = (iy0 >= 0), vy1 = (iy0 <= 62);
        const float w00 = (vy0 && vx0) ? wy0 * wx0 : 0.0f;
        const float w01 = (vy0 && vx1) ? wy0 * wx1 : 0.0f;
        const float w10 = (vy1 && vx0) ? wy1 * wx0 : 0.0f;
        const float w11 = (vy1 && vx1) ? wy1 * wx1 : 0.0f;
        const int x0c = max(ix0, 0),     x1c = min(ix0 + 1, DS - 1);
        const int y0c = max(iy0, 0),     y1c = min(iy0 + 1, DS - 1);
        const int i00 = y0c * DS + x0c, i01 = y0c * DS + x1c;
        const int i10 = y1c * DS + x0c, i11 = y1c * DS + x1c;
        const float4* __restrict__ base = reinterpret_cast<const float4*>(g_decoded)
                                          + (size_t)(b * TOPK + k) * DS * DS;
        const float4 t00 = __ldg(base + i00);
        const float4 t01 = __ldg(base + i01);
        const float4 t10 = __ldg(base + i10);
        const float4 t11 = __ldg(base + i11);

        const float s0 = t00.x * w00 + t01.x * w01 + t10.x * w10 + t11.x * w11;
        const float s1 = t00.y * w00 + t01.y * w01 + t10.y * w10 + t11.y * w11;
        const float s2 = t00.z * w00 + t01.z * w01 + t10.z * w10 + t11.z * w11;

        if (!(done & 1) && s0 != 0.0f) { r0 = s0; done |= 1; }
        if (!(done & 2) && s1 != 0.0f) { r1 = s1; done |= 2; }
        if (!(done & 4) && s2 != 0.0f) { r2 = s2; done |= 4; }
        if (done == 7) break;
    }

    const size_t pix = (size_t)y * IMG + x;
    out[((size_t)(b * 3 + 0) * IMG * IMG) + pix] = r0;
    out[((size_t)(b * 3 + 1) * IMG * IMG) + pix] = r1;
    out[((size_t)(b * 3 + 2) * IMG * IMG) + pix] = r2;
}

// ---------------------------------------------------------------------------
extern "C" void kernel_launch(void* const* d_in, const int* in_sizes, int n_in,
                              void* d_out, int out_size)
{
    const float* z_what    = (const float*)d_in[0];
    const float* z_where   = (const float*)d_in[1];
    const int*   z_present = (const int*)  d_in[2];
    const float* z_depth   = (const float*)d_in[3];
    const float* W0 = (const float*)d_in[4];  const float* b0 = (const float*)d_in[5];
    const float* W1 = (const float*)d_in[6];  const float* b1 = (const float*)d_in[7];
    const float* W2 = (const float*)d_in[8];  const float* b2 = (const float*)d_in[9];
    const float* W3 = (const float*)d_in[10]; const float* b3 = (const float*)d_in[11];
    const float* W4 = (const float*)d_in[12]; const float* b4 = (const float*)d_in[13];
    const float* W5 = (const float*)d_in[14]; const float* b5 = (const float*)d_in[15];
    float* out = (float*)d_out;

    decodeA_kernel<<<NOBJ, 256>>>(z_depth, z_what, W0, b0, W1, b1, W2, b2, W3, b3);

    decodeB_kernel<<<NOBJ * 4, 256>>>(W4, b4, W5, b5);

    dim3 cgrid(NTX * NTX, BATCH);
    composite_kernel<<<cgrid, 256>>>(z_where, z_present, out);
}